// round 13
// baseline (speedup 1.0000x reference)
#include <cuda_runtime.h>
#include <cuda_bf16.h>
#include <mma.h>
#include <cstdint>
#include <cstring>

using namespace nvcuda;

#define NN 4096
#define EMB 128
#define HH 128
#define EE 8
#define TT 2

typedef __nv_bfloat16 bf16;

// ---------------------------------------------------------------------------
// helpers
// ---------------------------------------------------------------------------
__device__ __forceinline__ void cp16(void* dst, const void* src) {
    unsigned d = (unsigned)__cvta_generic_to_shared(dst);
    asm volatile("cp.async.cg.shared.global [%0], [%1], 16;" :: "r"(d), "l"(src));
}
__device__ __forceinline__ void cp_commit() { asm volatile("cp.async.commit_group;"); }
template <int N> __device__ __forceinline__ void cp_wait() {
    asm volatile("cp.async.wait_group %0;" :: "n"(N));
}

__device__ __forceinline__ void split_bf16(float x, bf16& h, bf16& l) {
    h = __float2bfloat16(x);
    l = __float2bfloat16(x - __bfloat162float(h));
}
__device__ __forceinline__ uint32_t pack2(bf16 a, bf16 b) {
    return ((uint32_t)__bfloat16_as_ushort(b) << 16) | (uint32_t)__bfloat16_as_ushort(a);
}
__device__ __forceinline__ void sp2(float f0, float f1, uint32_t& hp, uint32_t& lp) {
    bf16 h0, l0, h1, l1;
    split_bf16(f0, h0, l0);
    split_bf16(f1, h1, l1);
    hp = pack2(h0, h1);
    lp = pack2(l0, l1);
}

__device__ __forceinline__ void mma16816v(float* c, const uint4& a, uint32_t b0, uint32_t b1) {
    asm volatile(
        "mma.sync.aligned.m16n8k16.row.col.f32.bf16.bf16.f32 "
        "{%0,%1,%2,%3}, {%4,%5,%6,%7}, {%8,%9}, {%0,%1,%2,%3};"
        : "+f"(c[0]), "+f"(c[1]), "+f"(c[2]), "+f"(c[3])
        : "r"(a.x), "r"(a.y), "r"(a.z), "r"(a.w), "r"(b0), "r"(b1));
}

// ---------------------------------------------------------------------------
// Scratch
// ---------------------------------------------------------------------------
__device__ bf16 g_adjPH[(long)EE * NN * NN];
__device__ bf16 g_adjPL[(long)EE * NN * NN];
__device__ bf16 g_adjTPH[(long)EE * NN * NN];
__device__ bf16 g_adjTPL[(long)EE * NN * NN];
// B-frag-packed interleaved hi/lo: per e, 16 nb x 256 K x 512B tiles
__device__ bf16 g_hoBP[(long)EE * HH * NN * 2];
__device__ bf16 g_hiBP[(long)EE * HH * NN * 2];
__device__ bf16 g_msgH[NN * 2048], g_msgL[NN * 2048];
__device__ bf16 g_hH[NN * HH], g_hL[NN * HH];
__device__ bf16 g_X0H[NN * 384], g_X0L[NN * 384];
__device__ bf16 g_WinitH[384 * HH], g_WinitL[384 * HH];
__device__ bf16 g_WoutH[EE * HH * HH], g_WoutL[EE * HH * HH];
__device__ bf16 g_WinH[EE * HH * HH], g_WinL[EE * HH * HH];
__device__ bf16 g_WxH[2048 * 384], g_WxL[2048 * 384];
__device__ bf16 g_WhH[HH * 384], g_WhL[HH * 384];
__device__ float g_hf[NN * HH];
__device__ float g_gi[NN * 384], g_gh[NN * 384];

// ---------------------------------------------------------------------------
// Fused prep: adjacency frag-pack (blocks < 32768) + weight split + gather
// ---------------------------------------------------------------------------
#define S0 12288L
#define S1 (S0 + 32768L)
#define S2 (S1 + 32768L)
#define S3 (S2 + 196608L)
#define S4 (S3 + 12288L)
#define PACK_BLOCKS 32768
#define PREP_TASKS (S4 + (long)NN * 384)

__global__ __launch_bounds__(256)
void prep_kernel(const float* __restrict__ adj,
                 char* __restrict__ aPH, char* __restrict__ aPL,
                 char* __restrict__ tPH, char* __restrict__ tPL,
                 const float4* w0, const float4* w1, const float4* w2,
                 const float4* w3, const float4* w4,
                 uint2* h0, uint2* l0, uint2* h1, uint2* l1,
                 uint2* h2, uint2* l2, uint2* h3, uint2* l3,
                 uint2* h4, uint2* l4,
                 const float* __restrict__ emb, const int* __restrict__ ids,
                 const float* __restrict__ states,
                 bf16* __restrict__ XH, bf16* __restrict__ XL) {
    __shared__ float sm[64][65];
    const int b = blockIdx.x;
    const int tid = threadIdx.x;

    if (b < PACK_BLOCKS) {
        const int e = b >> 12;
        const int rem = b & 4095;
        const int r0 = (rem >> 6) * 64, c0 = (rem & 63) * 64;
        const long base = (long)e * NN * NN;
        const long ebytes = base * 2;

#pragma unroll
        for (int it = 0; it < 4; it++) {
            int idx = tid + it * 256;
            int r = idx >> 4, c = (idx & 15) * 4;
            float4 v = *(const float4*)(adj + base + (long)(r0 + r) * NN + c0 + c);
            sm[r][c] = v.x; sm[r][c + 1] = v.y; sm[r][c + 2] = v.z; sm[r][c + 3] = v.w;
        }
        __syncthreads();

        const int wid = tid >> 5, lane = tid & 31;
        const int g = lane >> 2, t = lane & 3;

#pragma unroll
        for (int q = 0; q < 2; q++) {
            int ti = wid * 2 + q;
            int tr = ti >> 2, tc = ti & 3;
            {
                int rb = tr * 16, cb = tc * 16;
                uint4 H, L;
                sp2(sm[rb + g][cb + 2 * t],     sm[rb + g][cb + 2 * t + 1],     H.x, L.x);
                sp2(sm[rb + g + 8][cb + 2 * t], sm[rb + g + 8][cb + 2 * t + 1], H.y, L.y);
                sp2(sm[rb + g][cb + 2 * t + 8], sm[rb + g][cb + 2 * t + 9],     H.z, L.z);
                sp2(sm[rb + g + 8][cb + 2 * t + 8], sm[rb + g + 8][cb + 2 * t + 9], H.w, L.w);
                long R = (r0 >> 4) + tr, K = (c0 >> 4) + tc;
                long off = ebytes + (R * 256 + K) * 512 + lane * 16;
                *(uint4*)(aPH + off) = H;
                *(uint4*)(aPL + off) = L;
            }
            {
                int v = tr * 16, u = tc * 16;
                uint4 H, L;
                sp2(sm[v + 2 * t][u + g],         sm[v + 2 * t + 1][u + g],         H.x, L.x);
                sp2(sm[v + 2 * t][u + g + 8],     sm[v + 2 * t + 1][u + g + 8],     H.y, L.y);
                sp2(sm[v + 2 * t + 8][u + g],     sm[v + 2 * t + 9][u + g],         H.z, L.z);
                sp2(sm[v + 2 * t + 8][u + g + 8], sm[v + 2 * t + 9][u + g + 8],     H.w, L.w);
                long R2 = (c0 >> 4) + tc, K2 = (r0 >> 4) + tr;
                long off = ebytes + (R2 * 256 + K2) * 512 + lane * 16;
                *(uint4*)(tPH + off) = H;
                *(uint4*)(tPL + off) = L;
            }
        }
    } else {
        long i = (long)(b - PACK_BLOCKS) * 256 + tid;
        if (i < S4) {
            const float4* src; uint2 *dh, *dl; long o;
            if (i < S0)      { src = w0; dh = h0; dl = l0; o = i; }
            else if (i < S1) { src = w1; dh = h1; dl = l1; o = i - S0; }
            else if (i < S2) { src = w2; dh = h2; dl = l2; o = i - S1; }
            else if (i < S3) { src = w3; dh = h3; dl = l3; o = i - S2; }
            else             { src = w4; dh = h4; dl = l4; o = i - S3; }
            float4 v = src[o];
            uint2 H, L;
            sp2(v.x, v.y, H.x, L.x);
            sp2(v.z, v.w, H.y, L.y);
            dh[o] = H;
            dl[o] = L;
        } else if (i < PREP_TASKS) {
            long j = i - S4;
            int n = (int)(j / 384), c = (int)(j % 384);
            float v = (c < EMB) ? emb[(long)ids[n] * EMB + c]
                                : states[(long)n * (2 * EMB) + (c - EMB)];
            bf16 h, l;
            split_bf16(v, h, l);
            XH[j] = h;
            XL[j] = l;
        }
    }
}

// ---------------------------------------------------------------------------
// wmma GEMM (small GEMMs).
// modes: 0 = fp32 C; 3 = tanh+bias -> fp32 C + split bf16 CH/CL (row-major);
//        4 = tanh+bias -> B-frag-packed INTERLEAVED hi/lo (uint4/lane)
// dual: z in [0,16): z>=8 selects B2/bias2/C2H.
// ---------------------------------------------------------------------------
struct GP {
    const bf16 *AH, *AL, *BH, *BL, *B2H, *B2L;
    const float *bias, *bias2;
    float* C;
    bf16 *CH, *CL, *C2H, *C2L;
    int K, lda, ldb, ldc, mode, dual;
    long sB;
};

#define STAGES 4
#define ASZ 5120
#define BSZ 4352
#define STG (2 * ASZ + 2 * BSZ)
#define SMEM_BYTES (STAGES * STG * 2)

__global__ __launch_bounds__(256)
void gemm_k(GP p) {
    extern __shared__ char smemraw[];
    bf16* sm = (bf16*)smemraw;

    const int z = blockIdx.z;
    const bool second = p.dual && (z >= 8);
    const int e = p.dual ? (z & 7) : z;

    const bf16* AH = p.AH;
    const bf16* AL = p.AL;
    const bf16* BH = (second ? p.B2H : p.BH) + (long)e * p.sB;
    const bf16* BL = (second ? p.B2L : p.BL) + (long)e * p.sB;

    const int i0 = blockIdx.x * 128;
    const int j0 = blockIdx.y * 128;
    const int tid = threadIdx.x;
    const int wm = (tid >> 5) & 3;
    const int wn = tid >> 7;

    auto loadStage = [&](int s, int k0) {
        bf16* aH = sm + s * STG;
        bf16* aL = aH + ASZ;
        bf16* bH = aL + ASZ;
        bf16* bL = bH + BSZ;
#pragma unroll
        for (int t = 0; t < 2; t++) {
            int idx = tid + t * 256;
            int r = idx >> 2, c = (idx & 3) * 8;
            cp16(aH + r * 40 + c, AH + (long)(i0 + r) * p.lda + k0 + c);
            cp16(aL + r * 40 + c, AL + (long)(i0 + r) * p.lda + k0 + c);
        }
#pragma unroll
        for (int t = 0; t < 2; t++) {
            int idx = tid + t * 256;
            int r = idx >> 4, c = (idx & 15) * 8;
            cp16(bH + r * 136 + c, BH + (long)(k0 + r) * p.ldb + j0 + c);
            cp16(bL + r * 136 + c, BL + (long)(k0 + r) * p.ldb + j0 + c);
        }
    };

    wmma::fragment<wmma::accumulator, 16, 16, 16, float> acc[2][4];
#pragma unroll
    for (int m = 0; m < 2; m++)
#pragma unroll
        for (int n = 0; n < 4; n++)
            wmma::fill_fragment(acc[m][n], 0.0f);

    const int kIters = p.K / 32;
    for (int s = 0; s < STAGES - 1 && s < kIters; s++) {
        loadStage(s, s * 32);
        cp_commit();
    }

    for (int ki = 0; ki < kIters; ki++) {
        cp_wait<STAGES - 2>();
        __syncthreads();
        int ns = ki + STAGES - 1;
        if (ns < kIters) loadStage(ns % STAGES, ns * 32);
        cp_commit();

        bf16* aHB = sm + (ki % STAGES) * STG;
        bf16* aLB = aHB + ASZ;
        bf16* bHB = aLB + ASZ;
        bf16* bLB = bHB + BSZ;

#pragma unroll
        for (int ks = 0; ks < 32; ks += 16) {
            wmma::fragment<wmma::matrix_a, 16, 16, 16, bf16, wmma::row_major> ah[2], al[2];
            wmma::fragment<wmma::matrix_b, 16, 16, 16, bf16, wmma::row_major> bh[4], bl[4];
#pragma unroll
            for (int m = 0; m < 2; m++) {
                wmma::load_matrix_sync(ah[m], aHB + (wm * 32 + m * 16) * 40 + ks, 40);
                wmma::load_matrix_sync(al[m], aLB + (wm * 32 + m * 16) * 40 + ks, 40);
            }
#pragma unroll
            for (int n = 0; n < 4; n++) {
                wmma::load_matrix_sync(bh[n], bHB + ks * 136 + wn * 64 + n * 16, 136);
                wmma::load_matrix_sync(bl[n], bLB + ks * 136 + wn * 64 + n * 16, 136);
            }
#pragma unroll
            for (int n = 0; n < 4; n++)
#pragma unroll
                for (int m = 0; m < 2; m++) wmma::mma_sync(acc[m][n], ah[m], bh[n], acc[m][n]);
#pragma unroll
            for (int n = 0; n < 4; n++)
#pragma unroll
                for (int m = 0; m < 2; m++) wmma::mma_sync(acc[m][n], ah[m], bl[n], acc[m][n]);
#pragma unroll
            for (int n = 0; n < 4; n++)
#pragma unroll
                for (int m = 0; m < 2; m++) wmma::mma_sync(acc[m][n], al[m], bh[n], acc[m][n]);
        }
    }

    cp_wait<0>();
    __syncthreads();
    float* st = (float*)smemraw;
#pragma unroll
    for (int m = 0; m < 2; m++)
#pragma unroll
        for (int n = 0; n < 4; n++)
            wmma::store_matrix_sync(st + (wm * 32 + m * 16) * 132 + wn * 64 + n * 16,
                                    acc[m][n], 132, wmma::mem_row_major);
    __syncthreads();

    const float* bias = second ? p.bias2 : p.bias;
    bf16* CH = second ? p.C2H : p.CH;
    bf16* CL = second ? p.C2L : p.CL;

    if (p.mode == 4) {
        // B-frag-packed interleaved: tile 512B, lane uint4 = {bH0,bH1,bL0,bL1}
        char* CHc = (char*)CH;
#pragma unroll
        for (int it = 0; it < 16; it++) {
            int id = tid + it * 256;
            int lane = id & 31;
            int kb = (id >> 5) & 7;
            int nb = id >> 8;
            int g = lane >> 2, tt = lane & 3;
            int f = nb * 8 + g;
            float b = bias[e * 128 + f];
            float v00 = tanhf(st[(kb * 16 + 2 * tt) * 132 + f] + b);
            float v01 = tanhf(st[(kb * 16 + 2 * tt + 1) * 132 + f] + b);
            float v10 = tanhf(st[(kb * 16 + 2 * tt + 8) * 132 + f] + b);
            float v11 = tanhf(st[(kb * 16 + 2 * tt + 9) * 132 + f] + b);
            uint4 P;
            sp2(v00, v01, P.x, P.z);
            sp2(v10, v11, P.y, P.w);
            long Kglob = (i0 >> 4) + kb;
            long off = (long)e * HH * NN * 4 + ((long)nb * 256 + Kglob) * 512 + lane * 16;
            *(uint4*)(CHc + off) = P;
        }
    } else {
#pragma unroll
        for (int t = 0; t < 16; t++) {
            int idx = tid + t * 256;
            int r = idx >> 5, c = (idx & 31) * 4;
            float4 v = *(float4*)(st + r * 132 + c);
            float vv[4] = {v.x, v.y, v.z, v.w};
            if (p.mode == 3) {
#pragma unroll
                for (int j = 0; j < 4; j++)
                    vv[j] = tanhf(vv[j] + bias[j0 + c + j]);
            }
            long row = (long)(i0 + r) * p.ldc + j0 + c;
            *(float4*)(p.C + row) = make_float4(vv[0], vv[1], vv[2], vv[3]);
            if (p.mode == 3) {
                uint2 H, L;
                sp2(vv[0], vv[1], H.x, L.x);
                sp2(vv[2], vv[3], H.y, L.y);
                *(uint2*)(CH + row) = H;
                *(uint2*)(CL + row) = L;
            }
        }
    }
}

// ---------------------------------------------------------------------------
// Adjacency GEMM: register-direct mma.sync, register double-buffering,
// 256 threads, 2 CTAs/SM. CTA tile 64(M)x64(N), warps 2(M)x4(N),
// warp tile 32x16. grid (64, 2, 16) = 2048 CTAs -> ~1% wave-tail waste.
// z<8 : msg[:, e*128]      = adj[e]  @ ho[e]
// z>=8: msg[:, 1024+e*128] = adj[e]^T @ hi[e]
// Per iter per warp: 4x LDG.128 (A hi/lo) + 2x LDG.128 (B interleaved) + 12 mma.
// ---------------------------------------------------------------------------
#define ABLK 131072L   // bytes per 16-block across K (256 * 512)

__global__ __launch_bounds__(256, 2)
void adj_mma(const char* __restrict__ adjPH, const char* __restrict__ adjPL,
             const char* __restrict__ adjTPH, const char* __restrict__ adjTPL,
             const char* __restrict__ hoBP, const char* __restrict__ hiBP,
             bf16* __restrict__ msgH, bf16* __restrict__ msgL) {
    const int z = blockIdx.z;
    const bool second = z >= 8;
    const int e = z & 7;

    const char* AH = (second ? adjTPH : adjPH) + (long)e * NN * NN * 2;
    const char* AL = (second ? adjTPL : adjPL) + (long)e * NN * NN * 2;
    const char* B  = (second ? hiBP : hoBP) + (long)e * HH * NN * 4;
    const int coff = (second ? 1024 : 0) + e * 128;

    const int tid = threadIdx.x;
    const int wid = tid >> 5, lane = tid & 31;
    const int wm = wid >> 2;          // 0..1 (M)
    const int wn = wid & 3;           // 0..3 (N)
    const int g = lane >> 2, t = lane & 3;

    const long aBase = ((long)blockIdx.x * 4 + wm * 2) * ABLK + lane * 16;
    const long bBase = ((long)blockIdx.y * 8 + wn * 2) * ABLK + lane * 16;

    float acc[2][2][4];
#pragma unroll
    for (int m = 0; m < 2; m++)
#pragma unroll
        for (int n = 0; n < 2; n++)
#pragma unroll
            for (int q = 0; q < 4; q++) acc[m][n][q] = 0.0f;

    uint4 aHX[2], aLX[2], bX[2], aHY[2], aLY[2], bY[2];

    auto loadA = [&](uint4* aH, uint4* aL, int ki) {
        long o = aBase + (long)ki * 512;
#pragma unroll
        for (int mf = 0; mf < 2; mf++) {
            aH[mf] = *(const uint4*)(AH + o + mf * ABLK);
            aL[mf] = *(const uint4*)(AL + o + mf * ABLK);
        }
    };
    auto loadB = [&](uint4* b, int ki) {
        long o = bBase + (long)ki * 512;
#pragma unroll
        for (int nf = 0; nf < 2; nf++)
            b[nf] = *(const uint4*)(B + o + nf * ABLK);
    };
    auto domma = [&](const uint4* aH, const uint4* aL, const uint4* b) {
#pragma unroll
        for (int nf = 0; nf < 2; nf++)
#pragma unroll
            for (int mf = 0; mf < 2; mf++) mma16816v(acc[mf][nf], aH[mf], b[nf].x, b[nf].y);
#pragma unroll
        for (int nf = 0; nf < 2; nf++)
#pragma unroll
            for (int mf = 0; mf < 2; mf++) mma16816v(acc[mf][nf], aH[mf], b[nf].z, b[nf].w);
#pragma unroll
        for (int nf = 0; nf < 2; nf++)
#pragma unroll
            for (int mf = 0; mf < 2; mf++) mma16816v(acc[mf][nf], aL[mf], b[nf].x, b[nf].y);
    };

    loadA(aHX, aLX, 0);
    loadB(bX, 0);
    for (int ki = 0; ki < 256; ki += 2) {
        loadA(aHY, aLY, ki + 1);
        loadB(bY, ki + 1);
        domma(aHX, aLX, bX);
        if (ki + 2 < 256) {
            loadA(aHX, aLX, ki + 2);
            loadB(bX, ki + 2);
        }
        domma(aHY, aLY, bY);
    }

    // epilogue: c0=(g,2t) c1=(g,2t+1) c2=(g+8,2t) c3=(g+8,2t+1)
#pragma unroll
    for (int mf = 0; mf < 2; mf++) {
#pragma unroll
        for (int nf = 0; nf < 2; nf++) {
            const float* c = acc[mf][nf];
            int row = blockIdx.x * 64 + wm * 32 + mf * 16 + g;
            int col = coff + blockIdx.y * 64 + wn * 16 + nf * 8 + 2 * t;
            uint32_t H0, L0, H1, L1;
            sp2(c[0], c[1], H0, L0);
            sp2(c[2], c[3], H1, L1);
            long o0 = (long)row * 2048 + col;
            long o1 = (long)(row + 8) * 2048 + col;
            *(uint32_t*)(msgH + o0) = H0;
            *(uint32_t*)(msgL + o0) = L0;
            *(uint32_t*)(msgH + o1) = H1;
            *(uint32_t*)(msgL + o1) = L1;
        }
    }
}

// ---------------------------------------------------------------------------
// GRU + LayerNorm
// ---------------------------------------------------------------------------
__device__ __forceinline__ float block_sum128(float v, float* red) {
#pragma unroll
    for (int o = 16; o; o >>= 1) v += __shfl_xor_sync(0xffffffffu, v, o);
    int lane = threadIdx.x & 31, w = threadIdx.x >> 5;
    if (lane == 0) red[w] = v;
    __syncthreads();
    float s = red[0] + red[1] + red[2] + red[3];
    __syncthreads();
    return s;
}

__global__ void gru_kernel(const float* __restrict__ gi, const float* __restrict__ gh,
                           const float* __restrict__ h,
                           const float* __restrict__ bx, const float* __restrict__ bh,
                           const float* __restrict__ gamma, const float* __restrict__ beta,
                           float* __restrict__ out,
                           bf16* __restrict__ outH, bf16* __restrict__ outL) {
    __shared__ float red[4];
    const int n = blockIdx.x;
    const int k = threadIdx.x;

    float gi0 = gi[(long)n * 384 + k];
    float gi1 = gi[(long)n * 384 + 128 + k];
    float gi2 = gi[(long)n * 384 + 256 + k];
    float gh0 = gh[(long)n * 384 + k];
    float gh1 = gh[(long)n * 384 + 128 + k];
    float gh2 = gh[(long)n * 384 + 256 + k];

    float xr = gi0 + bx[k]       + gh0 + bh[k];
    float xz = gi1 + bx[128 + k] + gh1 + bh[128 + k];
    float xi = gi2 + bx[256 + k];
    float xh = gh2 + bh[256 + k];

    float mean = block_sum128(xr, red) * (1.0f / 128.0f);
    float d = xr - mean;
    float var = block_sum128(d * d, red) * (1.0f / 128.0f);
    float yr = d * rsqrtf(var + 1e-5f) * gamma[k] + beta[k];
    float r = 1.0f / (1.0f + expf(-yr));

    mean = block_sum128(xz, red) * (1.0f / 128.0f);
    d = xz - mean;
    var = block_sum128(d * d, red) * (1.0f / 128.0f);
    float yz = d * rsqrtf(var + 1e-5f) * gamma[128 + k] + beta[128 + k];
    float z = 1.0f / (1.0f + expf(-yz));

    float xn = xi + r * xh;
    mean = block_sum128(xn, red) * (1.0f / 128.0f);
    d = xn - mean;
    var = block_sum128(d * d, red) * (1.0f / 128.0f);
    float yn = d * rsqrtf(var + 1e-5f) * gamma[256 + k] + beta[256 + k];
    float nn_ = tanhf(yn);

    float hv = h[(long)n * 128 + k];
    float o = (1.0f - z) * nn_ + z * hv;
    out[(long)n * 128 + k] = o;
    bf16 hh, ll;
    split_bf16(o, hh, ll);
    outH[(long)n * 128 + k] = hh;
    outL[(long)n * 128 + k] = ll;
}

// ---------------------------------------------------------------------------
// launch
// ---------------------------------------------------------------------------
static inline GP zeroGP() { GP p; memset(&p, 0, sizeof(p)); return p; }

extern "C" void kernel_launch(void* const* d_in, const int* in_sizes, int n_in,
                              void* d_out, int out_size) {
    (void)in_sizes; (void)n_in; (void)out_size;

    const float* adj    = (const float*)d_in[0];
    const float* states = (const float*)d_in[1];
    const int*   ids    = (const int*)  d_in[2];
    const float* emb    = (const float*)d_in[3];
    const float* W_init = (const float*)d_in[4];
    const float* b_init = (const float*)d_in[5];
    const float* W_out  = (const float*)d_in[6];
    const float* b_out  = (const float*)d_in[7];
    const float* W_in   = (const float*)d_in[8];
    const float* b_in   = (const float*)d_in[9];
    const float* Wx     = (const float*)d_in[10];
    const float* bx     = (const float*)d_in[11];
    const float* Wh     = (const float*)d_in[12];
    const float* bh     = (const float*)d_in[13];
    const float* gamma  = (const float*)d_in[14];
    const float* beta   = (const float*)d_in[15];
    float* out = (float*)d_out;

    bf16 *adjPH, *adjPL, *adjTPH, *adjTPL, *hoBP, *hiBP;
    bf16 *msgH, *msgL, *hH, *hL, *X0H, *X0L;
    bf16 *WinitH, *WinitL, *WoutH, *WoutL, *WinH, *WinL, *WxH, *WxL, *WhH, *WhL;
    float *hf, *gi, *gh;
    cudaGetSymbolAddress((void**)&adjPH, g_adjPH);
    cudaGetSymbolAddress((void**)&adjPL, g_adjPL);
    cudaGetSymbolAddress((void**)&adjTPH, g_adjTPH);
    cudaGetSymbolAddress((void**)&adjTPL, g_adjTPL);
    cudaGetSymbolAddress((void**)&hoBP, g_hoBP);
    cudaGetSymbolAddress((void**)&hiBP, g_hiBP);
    cudaGetSymbolAddress((void**)&msgH, g_msgH);
    cudaGetSymbolAddress((void**)&msgL, g_msgL);
    cudaGetSymbolAddress((void**)&hH, g_hH);
    cudaGetSymbolAddress((void**)&hL, g_hL);
    cudaGetSymbolAddress((void**)&X0H, g_X0H);
    cudaGetSymbolAddress((void**)&X0L, g_X0L);
    cudaGetSymbolAddress((void**)&WinitH, g_WinitH);
    cudaGetSymbolAddress((void**)&WinitL, g_WinitL);
    cudaGetSymbolAddress((void**)&WoutH, g_WoutH);
    cudaGetSymbolAddress((void**)&WoutL, g_WoutL);
    cudaGetSymbolAddress((void**)&WinH, g_WinH);
    cudaGetSymbolAddress((void**)&WinL, g_WinL);
    cudaGetSymbolAddress((void**)&WxH, g_WxH);
    cudaGetSymbolAddress((void**)&WxL, g_WxL);
    cudaGetSymbolAddress((void**)&WhH, g_WhH);
    cudaGetSymbolAddress((void**)&WhL, g_WhL);
    cudaGetSymbolAddress((void**)&hf, g_hf);
    cudaGetSymbolAddress((void**)&gi, g_gi);
    cudaGetSymbolAddress((void**)&gh, g_gh);

    cudaFuncSetAttribute(gemm_k, cudaFuncAttributeMaxDynamicSharedMemorySize, SMEM_BYTES);

    // 0: fused prep (adjacency pack + weight split + gather)
    {
        unsigned prepBlocks = (unsigned)((PREP_TASKS + 255) / 256);
        prep_kernel<<<PACK_BLOCKS + prepBlocks, 256>>>(
            adj, (char*)adjPH, (char*)adjPL, (char*)adjTPH, (char*)adjTPL,
            (const float4*)W_init, (const float4*)W_out, (const float4*)W_in,
            (const float4*)Wx, (const float4*)Wh,
            (uint2*)WinitH, (uint2*)WinitL, (uint2*)WoutH, (uint2*)WoutL,
            (uint2*)WinH, (uint2*)WinL, (uint2*)WxH, (uint2*)WxL,
            (uint2*)WhH, (uint2*)WhL,
            emb, ids, states, X0H, X0L);
    }

    // 1: h0 = tanh(X0 @ W_init + b_init)
    {
        GP p = zeroGP();
        p.AH = X0H; p.AL = X0L; p.BH = WinitH; p.BL = WinitL;
        p.bias = b_init; p.C = hf; p.CH = hH; p.CL = hL;
        p.K = 384; p.lda = 384; p.ldb = 128; p.ldc = 128;
        p.mode = 3;
        gemm_k<<<dim3(NN / 128, 1, 1), 256, SMEM_BYTES>>>(p);
    }

    for (int t = 0; t < TT; t++) {
        // 2/7: hoBP/hiBP = B-frag-packed tanh(h @ W + b), fused z=16
        {
            GP p = zeroGP();
            p.AH = hH; p.AL = hL;
            p.BH = WoutH; p.BL = WoutL; p.B2H = WinH; p.B2L = WinL;
            p.bias = b_out; p.bias2 = b_in;
            p.CH = hoBP; p.C2H = hiBP;
            p.K = HH; p.lda = HH; p.ldb = HH; p.ldc = HH;
            p.sB = (long)HH * HH;
            p.mode = 4; p.dual = 1;
            gemm_k<<<dim3(NN / 128, 1, 16), 256, SMEM_BYTES>>>(p);
        }
        // 3/8: messages — 64x64 CTA tile, 2048 CTAs (PROFILED at t=0)
        adj_mma<<<dim3(NN / 64, 2, 16), 256>>>(
            (const char*)adjPH, (const char*)adjPL,
            (const char*)adjTPH, (const char*)adjTPL,
            (const char*)hoBP, (const char*)hiBP,
            msgH, msgL);
        // 4/9: gi = msg @ Wx
        {
            GP p = zeroGP();
            p.AH = msgH; p.AL = msgL; p.BH = WxH; p.BL = WxL;
            p.C = gi;
            p.K = 2048; p.lda = 2048; p.ldb = 384; p.ldc = 384;
            p.mode = 0;
            gemm_k<<<dim3(NN / 128, 3, 1), 256, SMEM_BYTES>>>(p);
        }
        // 5/10: gh = h @ Wh
        {
            GP p = zeroGP();
            p.AH = hH; p.AL = hL; p.BH = WhH; p.BL = WhL;
            p.C = gh;
            p.K = HH; p.lda = HH; p.ldb = 384; p.ldc = 384;
            p.mode = 0;
            gemm_k<<<dim3(NN / 128, 3, 1), 256, SMEM_BYTES>>>(p);
        }
        // 6/11: GRU
        float* hnext = (t == TT - 1) ? out : hf;
        gru_kernel<<<NN, 128>>>(gi, gh, hf, bx, bh, gamma, beta, hnext, hH, hL);
    }
}

// round 14
// speedup vs baseline: 1.0596x; 1.0596x over previous
#include <cuda_runtime.h>
#include <cuda_bf16.h>
#include <mma.h>
#include <cstdint>
#include <cstring>

using namespace nvcuda;

#define NN 4096
#define EMB 128
#define HH 128
#define EE 8
#define TT 2

typedef __nv_bfloat16 bf16;

// ---------------------------------------------------------------------------
// helpers
// ---------------------------------------------------------------------------
__device__ __forceinline__ void cp16(void* dst, const void* src) {
    unsigned d = (unsigned)__cvta_generic_to_shared(dst);
    asm volatile("cp.async.cg.shared.global [%0], [%1], 16;" :: "r"(d), "l"(src));
}
__device__ __forceinline__ void cp_commit() { asm volatile("cp.async.commit_group;"); }
template <int N> __device__ __forceinline__ void cp_wait() {
    asm volatile("cp.async.wait_group %0;" :: "n"(N));
}

__device__ __forceinline__ void split_bf16(float x, bf16& h, bf16& l) {
    h = __float2bfloat16(x);
    l = __float2bfloat16(x - __bfloat162float(h));
}
__device__ __forceinline__ uint32_t pack2(bf16 a, bf16 b) {
    return ((uint32_t)__bfloat16_as_ushort(b) << 16) | (uint32_t)__bfloat16_as_ushort(a);
}
__device__ __forceinline__ void sp2(float f0, float f1, uint32_t& hp, uint32_t& lp) {
    bf16 h0, l0, h1, l1;
    split_bf16(f0, h0, l0);
    split_bf16(f1, h1, l1);
    hp = pack2(h0, h1);
    lp = pack2(l0, l1);
}

__device__ __forceinline__ void mma16816v(float* c, const uint4& a, uint32_t b0, uint32_t b1) {
    asm volatile(
        "mma.sync.aligned.m16n8k16.row.col.f32.bf16.bf16.f32 "
        "{%0,%1,%2,%3}, {%4,%5,%6,%7}, {%8,%9}, {%0,%1,%2,%3};"
        : "+f"(c[0]), "+f"(c[1]), "+f"(c[2]), "+f"(c[3])
        : "r"(a.x), "r"(a.y), "r"(a.z), "r"(a.w), "r"(b0), "r"(b1));
}

// in-register A-fragment transpose: 16x16 tile = 4x 8x8 blocks; swap a1<->a2,
// movmatrix each block. Exact data movement (no rounding).
__device__ __forceinline__ uint32_t movm(uint32_t a) {
    uint32_t d;
    asm volatile("movmatrix.sync.aligned.m8n8.trans.b16 %0, %1;" : "=r"(d) : "r"(a));
    return d;
}
__device__ __forceinline__ uint4 transA(uint4 v) {
    uint4 r;
    r.x = movm(v.x);
    r.y = movm(v.z);
    r.z = movm(v.y);
    r.w = movm(v.w);
    return r;
}

// ---------------------------------------------------------------------------
// Scratch (no transposed adjacency copy anymore)
// ---------------------------------------------------------------------------
__device__ bf16 g_adjPH[(long)EE * NN * NN];
__device__ bf16 g_adjPL[(long)EE * NN * NN];
// B-frag-packed interleaved hi/lo: per e, 16 nb x 256 K x 512B tiles
__device__ bf16 g_hoBP[(long)EE * HH * NN * 2];
__device__ bf16 g_hiBP[(long)EE * HH * NN * 2];
__device__ bf16 g_msgH[NN * 2048], g_msgL[NN * 2048];
__device__ bf16 g_hH[NN * HH], g_hL[NN * HH];
__device__ bf16 g_X0H[NN * 384], g_X0L[NN * 384];
__device__ bf16 g_WinitH[384 * HH], g_WinitL[384 * HH];
__device__ bf16 g_WoutH[EE * HH * HH], g_WoutL[EE * HH * HH];
__device__ bf16 g_WinH[EE * HH * HH], g_WinL[EE * HH * HH];
__device__ bf16 g_WxH[2048 * 384], g_WxL[2048 * 384];
__device__ bf16 g_WhH[HH * 384], g_WhL[HH * 384];
__device__ float g_hf[NN * HH];
__device__ float g_gi[NN * 384], g_gh[NN * 384];

// ---------------------------------------------------------------------------
// Fused prep: adjacency frag-pack (normal only) + weight split + gather
// ---------------------------------------------------------------------------
#define S0 12288L
#define S1 (S0 + 32768L)
#define S2 (S1 + 32768L)
#define S3 (S2 + 196608L)
#define S4 (S3 + 12288L)
#define PACK_BLOCKS 32768
#define PREP_TASKS (S4 + (long)NN * 384)

__global__ __launch_bounds__(256)
void prep_kernel(const float* __restrict__ adj,
                 char* __restrict__ aPH, char* __restrict__ aPL,
                 const float4* w0, const float4* w1, const float4* w2,
                 const float4* w3, const float4* w4,
                 uint2* h0, uint2* l0, uint2* h1, uint2* l1,
                 uint2* h2, uint2* l2, uint2* h3, uint2* l3,
                 uint2* h4, uint2* l4,
                 const float* __restrict__ emb, const int* __restrict__ ids,
                 const float* __restrict__ states,
                 bf16* __restrict__ XH, bf16* __restrict__ XL) {
    __shared__ float sm[64][65];
    const int b = blockIdx.x;
    const int tid = threadIdx.x;

    if (b < PACK_BLOCKS) {
        const int e = b >> 12;
        const int rem = b & 4095;
        const int r0 = (rem >> 6) * 64, c0 = (rem & 63) * 64;
        const long base = (long)e * NN * NN;
        const long ebytes = base * 2;

#pragma unroll
        for (int it = 0; it < 4; it++) {
            int idx = tid + it * 256;
            int r = idx >> 4, c = (idx & 15) * 4;
            float4 v = *(const float4*)(adj + base + (long)(r0 + r) * NN + c0 + c);
            sm[r][c] = v.x; sm[r][c + 1] = v.y; sm[r][c + 2] = v.z; sm[r][c + 3] = v.w;
        }
        __syncthreads();

        const int wid = tid >> 5, lane = tid & 31;
        const int g = lane >> 2, t = lane & 3;

#pragma unroll
        for (int q = 0; q < 2; q++) {
            int ti = wid * 2 + q;
            int tr = ti >> 2, tc = ti & 3;
            int rb = tr * 16, cb = tc * 16;
            uint4 H, L;
            sp2(sm[rb + g][cb + 2 * t],     sm[rb + g][cb + 2 * t + 1],     H.x, L.x);
            sp2(sm[rb + g + 8][cb + 2 * t], sm[rb + g + 8][cb + 2 * t + 1], H.y, L.y);
            sp2(sm[rb + g][cb + 2 * t + 8], sm[rb + g][cb + 2 * t + 9],     H.z, L.z);
            sp2(sm[rb + g + 8][cb + 2 * t + 8], sm[rb + g + 8][cb + 2 * t + 9], H.w, L.w);
            long R = (r0 >> 4) + tr, K = (c0 >> 4) + tc;
            long off = ebytes + (R * 256 + K) * 512 + lane * 16;
            *(uint4*)(aPH + off) = H;
            *(uint4*)(aPL + off) = L;
        }
    } else {
        long i = (long)(b - PACK_BLOCKS) * 256 + tid;
        if (i < S4) {
            const float4* src; uint2 *dh, *dl; long o;
            if (i < S0)      { src = w0; dh = h0; dl = l0; o = i; }
            else if (i < S1) { src = w1; dh = h1; dl = l1; o = i - S0; }
            else if (i < S2) { src = w2; dh = h2; dl = l2; o = i - S1; }
            else if (i < S3) { src = w3; dh = h3; dl = l3; o = i - S2; }
            else             { src = w4; dh = h4; dl = l4; o = i - S3; }
            float4 v = src[o];
            uint2 H, L;
            sp2(v.x, v.y, H.x, L.x);
            sp2(v.z, v.w, H.y, L.y);
            dh[o] = H;
            dl[o] = L;
        } else if (i < PREP_TASKS) {
            long j = i - S4;
            int n = (int)(j / 384), c = (int)(j % 384);
            float v = (c < EMB) ? emb[(long)ids[n] * EMB + c]
                                : states[(long)n * (2 * EMB) + (c - EMB)];
            bf16 h, l;
            split_bf16(v, h, l);
            XH[j] = h;
            XL[j] = l;
        }
    }
}

// ---------------------------------------------------------------------------
// wmma GEMM (small GEMMs).
// modes: 0 = fp32 C; 3 = tanh+bias -> fp32 C + split bf16 CH/CL (row-major);
//        4 = tanh+bias -> B-frag-packed INTERLEAVED hi/lo (uint4/lane)
// dual: z in [0,16): z>=8 selects B2/bias2/C2H.
// ---------------------------------------------------------------------------
struct GP {
    const bf16 *AH, *AL, *BH, *BL, *B2H, *B2L;
    const float *bias, *bias2;
    float* C;
    bf16 *CH, *CL, *C2H, *C2L;
    int K, lda, ldb, ldc, mode, dual;
    long sB;
};

#define STAGES 4
#define ASZ 5120
#define BSZ 4352
#define STG (2 * ASZ + 2 * BSZ)
#define SMEM_BYTES (STAGES * STG * 2)

__global__ __launch_bounds__(256)
void gemm_k(GP p) {
    extern __shared__ char smemraw[];
    bf16* sm = (bf16*)smemraw;

    const int z = blockIdx.z;
    const bool second = p.dual && (z >= 8);
    const int e = p.dual ? (z & 7) : z;

    const bf16* AH = p.AH;
    const bf16* AL = p.AL;
    const bf16* BH = (second ? p.B2H : p.BH) + (long)e * p.sB;
    const bf16* BL = (second ? p.B2L : p.BL) + (long)e * p.sB;

    const int i0 = blockIdx.x * 128;
    const int j0 = blockIdx.y * 128;
    const int tid = threadIdx.x;
    const int wm = (tid >> 5) & 3;
    const int wn = tid >> 7;

    auto loadStage = [&](int s, int k0) {
        bf16* aH = sm + s * STG;
        bf16* aL = aH + ASZ;
        bf16* bH = aL + ASZ;
        bf16* bL = bH + BSZ;
#pragma unroll
        for (int t = 0; t < 2; t++) {
            int idx = tid + t * 256;
            int r = idx >> 2, c = (idx & 3) * 8;
            cp16(aH + r * 40 + c, AH + (long)(i0 + r) * p.lda + k0 + c);
            cp16(aL + r * 40 + c, AL + (long)(i0 + r) * p.lda + k0 + c);
        }
#pragma unroll
        for (int t = 0; t < 2; t++) {
            int idx = tid + t * 256;
            int r = idx >> 4, c = (idx & 15) * 8;
            cp16(bH + r * 136 + c, BH + (long)(k0 + r) * p.ldb + j0 + c);
            cp16(bL + r * 136 + c, BL + (long)(k0 + r) * p.ldb + j0 + c);
        }
    };

    wmma::fragment<wmma::accumulator, 16, 16, 16, float> acc[2][4];
#pragma unroll
    for (int m = 0; m < 2; m++)
#pragma unroll
        for (int n = 0; n < 4; n++)
            wmma::fill_fragment(acc[m][n], 0.0f);

    const int kIters = p.K / 32;
    for (int s = 0; s < STAGES - 1 && s < kIters; s++) {
        loadStage(s, s * 32);
        cp_commit();
    }

    for (int ki = 0; ki < kIters; ki++) {
        cp_wait<STAGES - 2>();
        __syncthreads();
        int ns = ki + STAGES - 1;
        if (ns < kIters) loadStage(ns % STAGES, ns * 32);
        cp_commit();

        bf16* aHB = sm + (ki % STAGES) * STG;
        bf16* aLB = aHB + ASZ;
        bf16* bHB = aLB + ASZ;
        bf16* bLB = bHB + BSZ;

#pragma unroll
        for (int ks = 0; ks < 32; ks += 16) {
            wmma::fragment<wmma::matrix_a, 16, 16, 16, bf16, wmma::row_major> ah[2], al[2];
            wmma::fragment<wmma::matrix_b, 16, 16, 16, bf16, wmma::row_major> bh[4], bl[4];
#pragma unroll
            for (int m = 0; m < 2; m++) {
                wmma::load_matrix_sync(ah[m], aHB + (wm * 32 + m * 16) * 40 + ks, 40);
                wmma::load_matrix_sync(al[m], aLB + (wm * 32 + m * 16) * 40 + ks, 40);
            }
#pragma unroll
            for (int n = 0; n < 4; n++) {
                wmma::load_matrix_sync(bh[n], bHB + ks * 136 + wn * 64 + n * 16, 136);
                wmma::load_matrix_sync(bl[n], bLB + ks * 136 + wn * 64 + n * 16, 136);
            }
#pragma unroll
            for (int n = 0; n < 4; n++)
#pragma unroll
                for (int m = 0; m < 2; m++) wmma::mma_sync(acc[m][n], ah[m], bh[n], acc[m][n]);
#pragma unroll
            for (int n = 0; n < 4; n++)
#pragma unroll
                for (int m = 0; m < 2; m++) wmma::mma_sync(acc[m][n], ah[m], bl[n], acc[m][n]);
#pragma unroll
            for (int n = 0; n < 4; n++)
#pragma unroll
                for (int m = 0; m < 2; m++) wmma::mma_sync(acc[m][n], al[m], bh[n], acc[m][n]);
        }
    }

    cp_wait<0>();
    __syncthreads();
    float* st = (float*)smemraw;
#pragma unroll
    for (int m = 0; m < 2; m++)
#pragma unroll
        for (int n = 0; n < 4; n++)
            wmma::store_matrix_sync(st + (wm * 32 + m * 16) * 132 + wn * 64 + n * 16,
                                    acc[m][n], 132, wmma::mem_row_major);
    __syncthreads();

    const float* bias = second ? p.bias2 : p.bias;
    bf16* CH = second ? p.C2H : p.CH;
    bf16* CL = second ? p.C2L : p.CL;

    if (p.mode == 4) {
        // B-frag-packed interleaved: tile 512B, lane uint4 = {bH0,bH1,bL0,bL1}
        char* CHc = (char*)CH;
#pragma unroll
        for (int it = 0; it < 16; it++) {
            int id = tid + it * 256;
            int lane = id & 31;
            int kb = (id >> 5) & 7;
            int nb = id >> 8;
            int g = lane >> 2, tt = lane & 3;
            int f = nb * 8 + g;
            float b = bias[e * 128 + f];
            float v00 = tanhf(st[(kb * 16 + 2 * tt) * 132 + f] + b);
            float v01 = tanhf(st[(kb * 16 + 2 * tt + 1) * 132 + f] + b);
            float v10 = tanhf(st[(kb * 16 + 2 * tt + 8) * 132 + f] + b);
            float v11 = tanhf(st[(kb * 16 + 2 * tt + 9) * 132 + f] + b);
            uint4 P;
            sp2(v00, v01, P.x, P.z);
            sp2(v10, v11, P.y, P.w);
            long Kglob = (i0 >> 4) + kb;
            long off = (long)e * HH * NN * 4 + ((long)nb * 256 + Kglob) * 512 + lane * 16;
            *(uint4*)(CHc + off) = P;
        }
    } else {
#pragma unroll
        for (int t = 0; t < 16; t++) {
            int idx = tid + t * 256;
            int r = idx >> 5, c = (idx & 31) * 4;
            float4 v = *(float4*)(st + r * 132 + c);
            float vv[4] = {v.x, v.y, v.z, v.w};
            if (p.mode == 3) {
#pragma unroll
                for (int j = 0; j < 4; j++)
                    vv[j] = tanhf(vv[j] + bias[j0 + c + j]);
            }
            long row = (long)(i0 + r) * p.ldc + j0 + c;
            *(float4*)(p.C + row) = make_float4(vv[0], vv[1], vv[2], vv[3]);
            if (p.mode == 3) {
                uint2 H, L;
                sp2(vv[0], vv[1], H.x, L.x);
                sp2(vv[2], vv[3], H.y, L.y);
                *(uint2*)(CH + row) = H;
                *(uint2*)(CL + row) = L;
            }
        }
    }
}

// ---------------------------------------------------------------------------
// Adjacency GEMM (R12 tiling): 256 thr, 2 CTAs/SM, CTA tile 128(M)x64(N),
// warps 4(M)x2(N), warp tile 32x32, register double-buffering.
// grid (32, 2, 16): z<8 : msg[:, e*128]      = adj[e]  @ ho[e]
//                   z>=8: msg[:, 1024+e*128] = adj[e]^T @ hi[e]
// Second pass reads the SAME adjP tiles (swapped indexing) and transposes
// A-fragments in-register via movmatrix — no adjT copy in memory.
// ---------------------------------------------------------------------------
#define ABLK 131072L   // bytes per 16-block row across K (256 tiles * 512B)

__global__ __launch_bounds__(256, 2)
void adj_mma(const char* __restrict__ adjPH, const char* __restrict__ adjPL,
             const char* __restrict__ hoBP, const char* __restrict__ hiBP,
             bf16* __restrict__ msgH, bf16* __restrict__ msgL) {
    const int z = blockIdx.z;
    const bool second = z >= 8;
    const int e = z & 7;

    const char* AH = adjPH + (long)e * NN * NN * 2;
    const char* AL = adjPL + (long)e * NN * NN * 2;
    const char* B  = (second ? hiBP : hoBP) + (long)e * HH * NN * 4;
    const int coff = (second ? 1024 : 0) + e * 128;

    const int tid = threadIdx.x;
    const int wid = tid >> 5, lane = tid & 31;
    const int wm = wid >> 1;          // 0..3 (M)
    const int wn = wid & 1;           // 0..1 (N)
    const int g = lane >> 2, t = lane & 3;

    const long Rblk = (long)blockIdx.x * 8 + wm * 2;   // output 16-row block
    // normal: tile(R,K) at (R*256+K)*512 ; transposed read: tile(K,R) at (K*256+R)*512
    const long aMf = second ? 512L : ABLK;
    const long aKi = second ? ABLK : 512L;
    const long aBase = Rblk * (second ? 512L : ABLK) + lane * 16;
    const long bBase = ((long)blockIdx.y * 8 + wn * 4) * ABLK + lane * 16;

    float acc[2][4][4];
#pragma unroll
    for (int m = 0; m < 2; m++)
#pragma unroll
        for (int n = 0; n < 4; n++)
#pragma unroll
            for (int q = 0; q < 4; q++) acc[m][n][q] = 0.0f;

    uint4 aHX[2], aLX[2], bX[4], aHY[2], aLY[2], bY[4];

    auto loadA = [&](uint4* aH, uint4* aL, int ki) {
        long o = aBase + (long)ki * aKi;
#pragma unroll
        for (int mf = 0; mf < 2; mf++) {
            aH[mf] = *(const uint4*)(AH + o + mf * aMf);
            aL[mf] = *(const uint4*)(AL + o + mf * aMf);
        }
        if (second) {
#pragma unroll
            for (int mf = 0; mf < 2; mf++) {
                aH[mf] = transA(aH[mf]);
                aL[mf] = transA(aL[mf]);
            }
        }
    };
    auto loadB = [&](uint4* b, int ki) {
        long o = bBase + (long)ki * 512;
#pragma unroll
        for (int nf = 0; nf < 4; nf++)
            b[nf] = *(const uint4*)(B + o + nf * ABLK);
    };
    auto domma = [&](const uint4* aH, const uint4* aL, const uint4* b) {
#pragma unroll
        for (int nf = 0; nf < 4; nf++)
#pragma unroll
            for (int mf = 0; mf < 2; mf++) mma16816v(acc[mf][nf], aH[mf], b[nf].x, b[nf].y);
#pragma unroll
        for (int nf = 0; nf < 4; nf++)
#pragma unroll
            for (int mf = 0; mf < 2; mf++) mma16816v(acc[mf][nf], aH[mf], b[nf].z, b[nf].w);
#pragma unroll
        for (int nf = 0; nf < 4; nf++)
#pragma unroll
            for (int mf = 0; mf < 2; mf++) mma16816v(acc[mf][nf], aL[mf], b[nf].x, b[nf].y);
    };

    loadA(aHX, aLX, 0);
    loadB(bX, 0);
    for (int ki = 0; ki < 256; ki += 2) {
        loadA(aHY, aLY, ki + 1);
        loadB(bY, ki + 1);
        domma(aHX, aLX, bX);
        if (ki + 2 < 256) {
            loadA(aHX, aLX, ki + 2);
            loadB(bX, ki + 2);
        }
        domma(aHY, aLY, bY);
    }

    // epilogue: c0=(g,2t) c1=(g,2t+1) c2=(g+8,2t) c3=(g+8,2t+1)
#pragma unroll
    for (int mf = 0; mf < 2; mf++) {
#pragma unroll
        for (int nf = 0; nf < 4; nf++) {
            const float* c = acc[mf][nf];
            int row = blockIdx.x * 128 + wm * 32 + mf * 16 + g;
            int col = coff + blockIdx.y * 64 + wn * 32 + nf * 8 + 2 * t;
            uint32_t H0, L0, H1, L1;
            sp2(c[0], c[1], H0, L0);
            sp2(c[2], c[3], H1, L1);
            long o0 = (long)row * 2048 + col;
            long o1 = (long)(row + 8) * 2048 + col;
            *(uint32_t*)(msgH + o0) = H0;
            *(uint32_t*)(msgL + o0) = L0;
            *(uint32_t*)(msgH + o1) = H1;
            *(uint32_t*)(msgL + o1) = L1;
        }
    }
}

// ---------------------------------------------------------------------------
// GRU + LayerNorm
// ---------------------------------------------------------------------------
__device__ __forceinline__ float block_sum128(float v, float* red) {
#pragma unroll
    for (int o = 16; o; o >>= 1) v += __shfl_xor_sync(0xffffffffu, v, o);
    int lane = threadIdx.x & 31, w = threadIdx.x >> 5;
    if (lane == 0) red[w] = v;
    __syncthreads();
    float s = red[0] + red[1] + red[2] + red[3];
    __syncthreads();
    return s;
}

__global__ void gru_kernel(const float* __restrict__ gi, const float* __restrict__ gh,
                           const float* __restrict__ h,
                           const float* __restrict__ bx, const float* __restrict__ bh,
                           const float* __restrict__ gamma, const float* __restrict__ beta,
                           float* __restrict__ out,
                           bf16* __restrict__ outH, bf16* __restrict__ outL) {
    __shared__ float red[4];
    const int n = blockIdx.x;
    const int k = threadIdx.x;

    float gi0 = gi[(long)n * 384 + k];
    float gi1 = gi[(long)n * 384 + 128 + k];
    float gi2 = gi[(long)n * 384 + 256 + k];
    float gh0 = gh[(long)n * 384 + k];
    float gh1 = gh[(long)n * 384 + 128 + k];
    float gh2 = gh[(long)n * 384 + 256 + k];

    float xr = gi0 + bx[k]       + gh0 + bh[k];
    float xz = gi1 + bx[128 + k] + gh1 + bh[128 + k];
    float xi = gi2 + bx[256 + k];
    float xh = gh2 + bh[256 + k];

    float mean = block_sum128(xr, red) * (1.0f / 128.0f);
    float d = xr - mean;
    float var = block_sum128(d * d, red) * (1.0f / 128.0f);
    float yr = d * rsqrtf(var + 1e-5f) * gamma[k] + beta[k];
    float r = 1.0f / (1.0f + expf(-yr));

    mean = block_sum128(xz, red) * (1.0f / 128.0f);
    d = xz - mean;
    var = block_sum128(d * d, red) * (1.0f / 128.0f);
    float yz = d * rsqrtf(var + 1e-5f) * gamma[128 + k] + beta[128 + k];
    float z = 1.0f / (1.0f + expf(-yz));

    float xn = xi + r * xh;
    mean = block_sum128(xn, red) * (1.0f / 128.0f);
    d = xn - mean;
    var = block_sum128(d * d, red) * (1.0f / 128.0f);
    float yn = d * rsqrtf(var + 1e-5f) * gamma[256 + k] + beta[256 + k];
    float nn_ = tanhf(yn);

    float hv = h[(long)n * 128 + k];
    float o = (1.0f - z) * nn_ + z * hv;
    out[(long)n * 128 + k] = o;
    bf16 hh, ll;
    split_bf16(o, hh, ll);
    outH[(long)n * 128 + k] = hh;
    outL[(long)n * 128 + k] = ll;
}

// ---------------------------------------------------------------------------
// launch
// ---------------------------------------------------------------------------
static inline GP zeroGP() { GP p; memset(&p, 0, sizeof(p)); return p; }

extern "C" void kernel_launch(void* const* d_in, const int* in_sizes, int n_in,
                              void* d_out, int out_size) {
    (void)in_sizes; (void)n_in; (void)out_size;

    const float* adj    = (const float*)d_in[0];
    const float* states = (const float*)d_in[1];
    const int*   ids    = (const int*)  d_in[2];
    const float* emb    = (const float*)d_in[3];
    const float* W_init = (const float*)d_in[4];
    const float* b_init = (const float*)d_in[5];
    const float* W_out  = (const float*)d_in[6];
    const float* b_out  = (const float*)d_in[7];
    const float* W_in   = (const float*)d_in[8];
    const float* b_in   = (const float*)d_in[9];
    const float* Wx     = (const float*)d_in[10];
    const float* bx     = (const float*)d_in[11];
    const float* Wh     = (const float*)d_in[12];
    const float* bh     = (const float*)d_in[13];
    const float* gamma  = (const float*)d_in[14];
    const float* beta   = (const float*)d_in[15];
    float* out = (float*)d_out;

    bf16 *adjPH, *adjPL, *hoBP, *hiBP;
    bf16 *msgH, *msgL, *hH, *hL, *X0H, *X0L;
    bf16 *WinitH, *WinitL, *WoutH, *WoutL, *WinH, *WinL, *WxH, *WxL, *WhH, *WhL;
    float *hf, *gi, *gh;
    cudaGetSymbolAddress((void**)&adjPH, g_adjPH);
    cudaGetSymbolAddress((void**)&adjPL, g_adjPL);
    cudaGetSymbolAddress((void**)&hoBP, g_hoBP);
    cudaGetSymbolAddress((void**)&hiBP, g_hiBP);
    cudaGetSymbolAddress((void**)&msgH, g_msgH);
    cudaGetSymbolAddress((void**)&msgL, g_msgL);
    cudaGetSymbolAddress((void**)&hH, g_hH);
    cudaGetSymbolAddress((void**)&hL, g_hL);
    cudaGetSymbolAddress((void**)&X0H, g_X0H);
    cudaGetSymbolAddress((void**)&X0L, g_X0L);
    cudaGetSymbolAddress((void**)&WinitH, g_WinitH);
    cudaGetSymbolAddress((void**)&WinitL, g_WinitL);
    cudaGetSymbolAddress((void**)&WoutH, g_WoutH);
    cudaGetSymbolAddress((void**)&WoutL, g_WoutL);
    cudaGetSymbolAddress((void**)&WinH, g_WinH);
    cudaGetSymbolAddress((void**)&WinL, g_WinL);
    cudaGetSymbolAddress((void**)&WxH, g_WxH);
    cudaGetSymbolAddress((void**)&WxL, g_WxL);
    cudaGetSymbolAddress((void**)&WhH, g_WhH);
    cudaGetSymbolAddress((void**)&WhL, g_WhL);
    cudaGetSymbolAddress((void**)&hf, g_hf);
    cudaGetSymbolAddress((void**)&gi, g_gi);
    cudaGetSymbolAddress((void**)&gh, g_gh);

    cudaFuncSetAttribute(gemm_k, cudaFuncAttributeMaxDynamicSharedMemorySize, SMEM_BYTES);

    // 0: fused prep (adjacency pack + weight split + gather)
    {
        unsigned prepBlocks = (unsigned)((PREP_TASKS + 255) / 256);
        prep_kernel<<<PACK_BLOCKS + prepBlocks, 256>>>(
            adj, (char*)adjPH, (char*)adjPL,
            (const float4*)W_init, (const float4*)W_out, (const float4*)W_in,
            (const float4*)Wx, (const float4*)Wh,
            (uint2*)WinitH, (uint2*)WinitL, (uint2*)WoutH, (uint2*)WoutL,
            (uint2*)WinH, (uint2*)WinL, (uint2*)WxH, (uint2*)WxL,
            (uint2*)WhH, (uint2*)WhL,
            emb, ids, states, X0H, X0L);
    }

    // 1: h0 = tanh(X0 @ W_init + b_init)
    {
        GP p = zeroGP();
        p.AH = X0H; p.AL = X0L; p.BH = WinitH; p.BL = WinitL;
        p.bias = b_init; p.C = hf; p.CH = hH; p.CL = hL;
        p.K = 384; p.lda = 384; p.ldb = 128; p.ldc = 128;
        p.mode = 3;
        gemm_k<<<dim3(NN / 128, 1, 1), 256, SMEM_BYTES>>>(p);
    }

    for (int t = 0; t < TT; t++) {
        // 2/7: hoBP/hiBP = B-frag-packed tanh(h @ W + b), fused z=16
        {
            GP p = zeroGP();
            p.AH = hH; p.AL = hL;
            p.BH = WoutH; p.BL = WoutL; p.B2H = WinH; p.B2L = WinL;
            p.bias = b_out; p.bias2 = b_in;
            p.CH = hoBP; p.C2H = hiBP;
            p.K = HH; p.lda = HH; p.ldb = HH; p.ldc = HH;
            p.sB = (long)HH * HH;
            p.mode = 4; p.dual = 1;
            gemm_k<<<dim3(NN / 128, 1, 16), 256, SMEM_BYTES>>>(p);
        }
        // 3/8: messages — R12 tiling + movmatrix transposed pass (PROFILED t=0)
        adj_mma<<<dim3(NN / 128, 2, 16), 256>>>(
            (const char*)adjPH, (const char*)adjPL,
            (const char*)hoBP, (const char*)hiBP,
            msgH, msgL);
        // 4/9: gi = msg @ Wx
        {
            GP p = zeroGP();
            p.AH = msgH; p.AL = msgL; p.BH = WxH; p.BL = WxL;
            p.C = gi;
            p.K = 2048; p.lda = 2048; p.ldb = 384; p.ldc = 384;
            p.mode = 0;
            gemm_k<<<dim3(NN / 128, 3, 1), 256, SMEM_BYTES>>>(p);
        }
        // 5/10: gh = h @ Wh
        {
            GP p = zeroGP();
            p.AH = hH; p.AL = hL; p.BH = WhH; p.BL = WhL;
            p.C = gh;
            p.K = HH; p.lda = HH; p.ldb = 384; p.ldc = 384;
            p.mode = 0;
            gemm_k<<<dim3(NN / 128, 3, 1), 256, SMEM_BYTES>>>(p);
        }
        // 6/11: GRU
        float* hnext = (t == TT - 1) ? out : hf;
        gru_kernel<<<NN, 128>>>(gi, gh, hf, bx, bh, gamma, beta, hnext, hH, hL);
    }
}

// round 15
// speedup vs baseline: 1.2703x; 1.1989x over previous
#include <cuda_runtime.h>
#include <cuda_bf16.h>
#include <mma.h>
#include <cstdint>
#include <cstring>

using namespace nvcuda;

#define NN 4096
#define EMB 128
#define HH 128
#define EE 8
#define TT 2

typedef __nv_bfloat16 bf16;

// ---------------------------------------------------------------------------
// helpers
// ---------------------------------------------------------------------------
__device__ __forceinline__ void cp16(void* dst, const void* src) {
    unsigned d = (unsigned)__cvta_generic_to_shared(dst);
    asm volatile("cp.async.cg.shared.global [%0], [%1], 16;" :: "r"(d), "l"(src));
}
__device__ __forceinline__ void cp_commit() { asm volatile("cp.async.commit_group;"); }
template <int N> __device__ __forceinline__ void cp_wait() {
    asm volatile("cp.async.wait_group %0;" :: "n"(N));
}

__device__ __forceinline__ void split_bf16(float x, bf16& h, bf16& l) {
    h = __float2bfloat16(x);
    l = __float2bfloat16(x - __bfloat162float(h));
}
__device__ __forceinline__ uint32_t pack2(bf16 a, bf16 b) {
    return ((uint32_t)__bfloat16_as_ushort(b) << 16) | (uint32_t)__bfloat16_as_ushort(a);
}
__device__ __forceinline__ void sp2(float f0, float f1, uint32_t& hp, uint32_t& lp) {
    bf16 h0, l0, h1, l1;
    split_bf16(f0, h0, l0);
    split_bf16(f1, h1, l1);
    hp = pack2(h0, h1);
    lp = pack2(l0, l1);
}

__device__ __forceinline__ void mma16816v(float* c, const uint4& a, uint32_t b0, uint32_t b1) {
    asm volatile(
        "mma.sync.aligned.m16n8k16.row.col.f32.bf16.bf16.f32 "
        "{%0,%1,%2,%3}, {%4,%5,%6,%7}, {%8,%9}, {%0,%1,%2,%3};"
        : "+f"(c[0]), "+f"(c[1]), "+f"(c[2]), "+f"(c[3])
        : "r"(a.x), "r"(a.y), "r"(a.z), "r"(a.w), "r"(b0), "r"(b1));
}

// ---------------------------------------------------------------------------
// Scratch
// ---------------------------------------------------------------------------
__device__ bf16 g_adjPH[(long)EE * NN * NN];
__device__ bf16 g_adjPL[(long)EE * NN * NN];
__device__ bf16 g_adjTPH[(long)EE * NN * NN];
__device__ bf16 g_adjTPL[(long)EE * NN * NN];
// B-frag-packed interleaved hi/lo: per e, 16 nb x 256 K x 512B tiles
__device__ bf16 g_hoBP[(long)EE * HH * NN * 2];
__device__ bf16 g_hiBP[(long)EE * HH * NN * 2];
__device__ bf16 g_msgH[NN * 2048], g_msgL[NN * 2048];
__device__ bf16 g_hH[NN * HH], g_hL[NN * HH];
__device__ bf16 g_X0H[NN * 384], g_X0L[NN * 384];
__device__ bf16 g_WinitH[384 * HH], g_WinitL[384 * HH];
__device__ bf16 g_WoutH[EE * HH * HH], g_WoutL[EE * HH * HH];
__device__ bf16 g_WinH[EE * HH * HH], g_WinL[EE * HH * HH];
__device__ bf16 g_WxH[2048 * 384], g_WxL[2048 * 384];
__device__ bf16 g_WhH[HH * 384], g_WhL[HH * 384];
__device__ float g_hf[NN * HH];
__device__ float g_gi[NN * 384], g_gh[NN * 384];

// ---------------------------------------------------------------------------
// Fused prep: adjacency frag-pack (normal + transposed) + weight split + gather
// ---------------------------------------------------------------------------
#define S0 12288L
#define S1 (S0 + 32768L)
#define S2 (S1 + 32768L)
#define S3 (S2 + 196608L)
#define S4 (S3 + 12288L)
#define PACK_BLOCKS 32768
#define PREP_TASKS (S4 + (long)NN * 384)

__global__ __launch_bounds__(256)
void prep_kernel(const float* __restrict__ adj,
                 char* __restrict__ aPH, char* __restrict__ aPL,
                 char* __restrict__ tPH, char* __restrict__ tPL,
                 const float4* w0, const float4* w1, const float4* w2,
                 const float4* w3, const float4* w4,
                 uint2* h0, uint2* l0, uint2* h1, uint2* l1,
                 uint2* h2, uint2* l2, uint2* h3, uint2* l3,
                 uint2* h4, uint2* l4,
                 const float* __restrict__ emb, const int* __restrict__ ids,
                 const float* __restrict__ states,
                 bf16* __restrict__ XH, bf16* __restrict__ XL) {
    __shared__ float sm[64][65];
    const int b = blockIdx.x;
    const int tid = threadIdx.x;

    if (b < PACK_BLOCKS) {
        const int e = b >> 12;
        const int rem = b & 4095;
        const int r0 = (rem >> 6) * 64, c0 = (rem & 63) * 64;
        const long base = (long)e * NN * NN;
        const long ebytes = base * 2;

#pragma unroll
        for (int it = 0; it < 4; it++) {
            int idx = tid + it * 256;
            int r = idx >> 4, c = (idx & 15) * 4;
            float4 v = *(const float4*)(adj + base + (long)(r0 + r) * NN + c0 + c);
            sm[r][c] = v.x; sm[r][c + 1] = v.y; sm[r][c + 2] = v.z; sm[r][c + 3] = v.w;
        }
        __syncthreads();

        const int wid = tid >> 5, lane = tid & 31;
        const int g = lane >> 2, t = lane & 3;

#pragma unroll
        for (int q = 0; q < 2; q++) {
            int ti = wid * 2 + q;
            int tr = ti >> 2, tc = ti & 3;
            {
                int rb = tr * 16, cb = tc * 16;
                uint4 H, L;
                sp2(sm[rb + g][cb + 2 * t],     sm[rb + g][cb + 2 * t + 1],     H.x, L.x);
                sp2(sm[rb + g + 8][cb + 2 * t], sm[rb + g + 8][cb + 2 * t + 1], H.y, L.y);
                sp2(sm[rb + g][cb + 2 * t + 8], sm[rb + g][cb + 2 * t + 9],     H.z, L.z);
                sp2(sm[rb + g + 8][cb + 2 * t + 8], sm[rb + g + 8][cb + 2 * t + 9], H.w, L.w);
                long R = (r0 >> 4) + tr, K = (c0 >> 4) + tc;
                long off = ebytes + (R * 256 + K) * 512 + lane * 16;
                *(uint4*)(aPH + off) = H;
                *(uint4*)(aPL + off) = L;
            }
            {
                int v = tr * 16, u = tc * 16;
                uint4 H, L;
                sp2(sm[v + 2 * t][u + g],         sm[v + 2 * t + 1][u + g],         H.x, L.x);
                sp2(sm[v + 2 * t][u + g + 8],     sm[v + 2 * t + 1][u + g + 8],     H.y, L.y);
                sp2(sm[v + 2 * t + 8][u + g],     sm[v + 2 * t + 9][u + g],         H.z, L.z);
                sp2(sm[v + 2 * t + 8][u + g + 8], sm[v + 2 * t + 9][u + g + 8],     H.w, L.w);
                long R2 = (c0 >> 4) + tc, K2 = (r0 >> 4) + tr;
                long off = ebytes + (R2 * 256 + K2) * 512 + lane * 16;
                *(uint4*)(tPH + off) = H;
                *(uint4*)(tPL + off) = L;
            }
        }
    } else {
        long i = (long)(b - PACK_BLOCKS) * 256 + tid;
        if (i < S4) {
            const float4* src; uint2 *dh, *dl; long o;
            if (i < S0)      { src = w0; dh = h0; dl = l0; o = i; }
            else if (i < S1) { src = w1; dh = h1; dl = l1; o = i - S0; }
            else if (i < S2) { src = w2; dh = h2; dl = l2; o = i - S1; }
            else if (i < S3) { src = w3; dh = h3; dl = l3; o = i - S2; }
            else             { src = w4; dh = h4; dl = l4; o = i - S3; }
            float4 v = src[o];
            uint2 H, L;
            sp2(v.x, v.y, H.x, L.x);
            sp2(v.z, v.w, H.y, L.y);
            dh[o] = H;
            dl[o] = L;
        } else if (i < PREP_TASKS) {
            long j = i - S4;
            int n = (int)(j / 384), c = (int)(j % 384);
            float v = (c < EMB) ? emb[(long)ids[n] * EMB + c]
                                : states[(long)n * (2 * EMB) + (c - EMB)];
            bf16 h, l;
            split_bf16(v, h, l);
            XH[j] = h;
            XL[j] = l;
        }
    }
}

// ---------------------------------------------------------------------------
// wmma GEMM (small GEMMs). 3 stages + 2 CTAs/SM for doubled TLP.
// modes: 0 = fp32 C; 3 = tanh+bias -> fp32 C + split bf16 CH/CL (row-major);
//        4 = tanh+bias -> B-frag-packed INTERLEAVED hi/lo (uint4/lane)
// dual: z in [0,16): z>=8 selects B2/bias2/C2H.
// ---------------------------------------------------------------------------
struct GP {
    const bf16 *AH, *AL, *BH, *BL, *B2H, *B2L;
    const float *bias, *bias2;
    float* C;
    bf16 *CH, *CL, *C2H, *C2L;
    int K, lda, ldb, ldc, mode, dual;
    long sB;
};

#define STAGES 3
#define ASZ 5120
#define BSZ 4352
#define STG (2 * ASZ + 2 * BSZ)
#define SMEM_BYTES (STAGES * STG * 2)   // 113664 bytes -> 2 CTAs/SM

__global__ __launch_bounds__(256, 2)
void gemm_k(GP p) {
    extern __shared__ char smemraw[];
    bf16* sm = (bf16*)smemraw;

    const int z = blockIdx.z;
    const bool second = p.dual && (z >= 8);
    const int e = p.dual ? (z & 7) : z;

    const bf16* AH = p.AH;
    const bf16* AL = p.AL;
    const bf16* BH = (second ? p.B2H : p.BH) + (long)e * p.sB;
    const bf16* BL = (second ? p.B2L : p.BL) + (long)e * p.sB;

    const int i0 = blockIdx.x * 128;
    const int j0 = blockIdx.y * 128;
    const int tid = threadIdx.x;
    const int wm = (tid >> 5) & 3;
    const int wn = tid >> 7;

    auto loadStage = [&](int s, int k0) {
        bf16* aH = sm + s * STG;
        bf16* aL = aH + ASZ;
        bf16* bH = aL + ASZ;
        bf16* bL = bH + BSZ;
#pragma unroll
        for (int t = 0; t < 2; t++) {
            int idx = tid + t * 256;
            int r = idx >> 2, c = (idx & 3) * 8;
            cp16(aH + r * 40 + c, AH + (long)(i0 + r) * p.lda + k0 + c);
            cp16(aL + r * 40 + c, AL + (long)(i0 + r) * p.lda + k0 + c);
        }
#pragma unroll
        for (int t = 0; t < 2; t++) {
            int idx = tid + t * 256;
            int r = idx >> 4, c = (idx & 15) * 8;
            cp16(bH + r * 136 + c, BH + (long)(k0 + r) * p.ldb + j0 + c);
            cp16(bL + r * 136 + c, BL + (long)(k0 + r) * p.ldb + j0 + c);
        }
    };

    wmma::fragment<wmma::accumulator, 16, 16, 16, float> acc[2][4];
#pragma unroll
    for (int m = 0; m < 2; m++)
#pragma unroll
        for (int n = 0; n < 4; n++)
            wmma::fill_fragment(acc[m][n], 0.0f);

    const int kIters = p.K / 32;
    for (int s = 0; s < STAGES - 1 && s < kIters; s++) {
        loadStage(s, s * 32);
        cp_commit();
    }

    for (int ki = 0; ki < kIters; ki++) {
        cp_wait<STAGES - 2>();
        __syncthreads();
        int ns = ki + STAGES - 1;
        if (ns < kIters) loadStage(ns % STAGES, ns * 32);
        cp_commit();

        bf16* aHB = sm + (ki % STAGES) * STG;
        bf16* aLB = aHB + ASZ;
        bf16* bHB = aLB + ASZ;
        bf16* bLB = bHB + BSZ;

#pragma unroll
        for (int ks = 0; ks < 32; ks += 16) {
            wmma::fragment<wmma::matrix_a, 16, 16, 16, bf16, wmma::row_major> ah[2], al[2];
            wmma::fragment<wmma::matrix_b, 16, 16, 16, bf16, wmma::row_major> bh[4], bl[4];
#pragma unroll
            for (int m = 0; m < 2; m++) {
                wmma::load_matrix_sync(ah[m], aHB + (wm * 32 + m * 16) * 40 + ks, 40);
                wmma::load_matrix_sync(al[m], aLB + (wm * 32 + m * 16) * 40 + ks, 40);
            }
#pragma unroll
            for (int n = 0; n < 4; n++) {
                wmma::load_matrix_sync(bh[n], bHB + ks * 136 + wn * 64 + n * 16, 136);
                wmma::load_matrix_sync(bl[n], bLB + ks * 136 + wn * 64 + n * 16, 136);
            }
#pragma unroll
            for (int n = 0; n < 4; n++)
#pragma unroll
                for (int m = 0; m < 2; m++) wmma::mma_sync(acc[m][n], ah[m], bh[n], acc[m][n]);
#pragma unroll
            for (int n = 0; n < 4; n++)
#pragma unroll
                for (int m = 0; m < 2; m++) wmma::mma_sync(acc[m][n], ah[m], bl[n], acc[m][n]);
#pragma unroll
            for (int n = 0; n < 4; n++)
#pragma unroll
                for (int m = 0; m < 2; m++) wmma::mma_sync(acc[m][n], al[m], bh[n], acc[m][n]);
        }
    }

    cp_wait<0>();
    __syncthreads();
    float* st = (float*)smemraw;
#pragma unroll
    for (int m = 0; m < 2; m++)
#pragma unroll
        for (int n = 0; n < 4; n++)
            wmma::store_matrix_sync(st + (wm * 32 + m * 16) * 132 + wn * 64 + n * 16,
                                    acc[m][n], 132, wmma::mem_row_major);
    __syncthreads();

    const float* bias = second ? p.bias2 : p.bias;
    bf16* CH = second ? p.C2H : p.CH;
    bf16* CL = second ? p.C2L : p.CL;

    if (p.mode == 4) {
        // B-frag-packed interleaved: tile 512B, lane uint4 = {bH0,bH1,bL0,bL1}
        char* CHc = (char*)CH;
#pragma unroll
        for (int it = 0; it < 16; it++) {
            int id = tid + it * 256;
            int lane = id & 31;
            int kb = (id >> 5) & 7;
            int nb = id >> 8;
            int g = lane >> 2, tt = lane & 3;
            int f = nb * 8 + g;
            float b = bias[e * 128 + f];
            float v00 = tanhf(st[(kb * 16 + 2 * tt) * 132 + f] + b);
            float v01 = tanhf(st[(kb * 16 + 2 * tt + 1) * 132 + f] + b);
            float v10 = tanhf(st[(kb * 16 + 2 * tt + 8) * 132 + f] + b);
            float v11 = tanhf(st[(kb * 16 + 2 * tt + 9) * 132 + f] + b);
            uint4 P;
            sp2(v00, v01, P.x, P.z);
            sp2(v10, v11, P.y, P.w);
            long Kglob = (i0 >> 4) + kb;
            long off = (long)e * HH * NN * 4 + ((long)nb * 256 + Kglob) * 512 + lane * 16;
            *(uint4*)(CHc + off) = P;
        }
    } else {
#pragma unroll
        for (int t = 0; t < 16; t++) {
            int idx = tid + t * 256;
            int r = idx >> 5, c = (idx & 31) * 4;
            float4 v = *(float4*)(st + r * 132 + c);
            float vv[4] = {v.x, v.y, v.z, v.w};
            if (p.mode == 3) {
#pragma unroll
                for (int j = 0; j < 4; j++)
                    vv[j] = tanhf(vv[j] + bias[j0 + c + j]);
            }
            long row = (long)(i0 + r) * p.ldc + j0 + c;
            *(float4*)(p.C + row) = make_float4(vv[0], vv[1], vv[2], vv[3]);
            if (p.mode == 3) {
                uint2 H, L;
                sp2(vv[0], vv[1], H.x, L.x);
                sp2(vv[2], vv[3], H.y, L.y);
                *(uint2*)(CH + row) = H;
                *(uint2*)(CL + row) = L;
            }
        }
    }
}

// ---------------------------------------------------------------------------
// Adjacency GEMM (R12 exact): 256 thr, 2 CTAs/SM, CTA tile 128(M)x64(N),
// warps 4(M)x2(N), warp tile 32x32, register double-buffering.
// grid (32, 2, 16): z<8 : msg[:, e*128]      = adj[e]  @ ho[e]
//                   z>=8: msg[:, 1024+e*128] = adj[e]^T @ hi[e]
// Per iter per warp: 4x LDG.128 (A hi/lo) + 4x LDG.128 (B interleaved) + 24 mma.
// ---------------------------------------------------------------------------
#define ABLK 131072L   // bytes per 16-block across K (256 * 512)

__global__ __launch_bounds__(256, 2)
void adj_mma(const char* __restrict__ adjPH, const char* __restrict__ adjPL,
             const char* __restrict__ adjTPH, const char* __restrict__ adjTPL,
             const char* __restrict__ hoBP, const char* __restrict__ hiBP,
             bf16* __restrict__ msgH, bf16* __restrict__ msgL) {
    const int z = blockIdx.z;
    const bool second = z >= 8;
    const int e = z & 7;

    const char* AH = (second ? adjTPH : adjPH) + (long)e * NN * NN * 2;
    const char* AL = (second ? adjTPL : adjPL) + (long)e * NN * NN * 2;
    const char* B  = (second ? hiBP : hoBP) + (long)e * HH * NN * 4;
    const int coff = (second ? 1024 : 0) + e * 128;

    const int tid = threadIdx.x;
    const int wid = tid >> 5, lane = tid & 31;
    const int wm = wid >> 1;          // 0..3 (M)
    const int wn = wid & 1;           // 0..1 (N)
    const int g = lane >> 2, t = lane & 3;

    const long aBase = ((long)blockIdx.x * 8 + wm * 2) * ABLK + lane * 16;
    const long bBase = ((long)blockIdx.y * 8 + wn * 4) * ABLK + lane * 16;

    float acc[2][4][4];
#pragma unroll
    for (int m = 0; m < 2; m++)
#pragma unroll
        for (int n = 0; n < 4; n++)
#pragma unroll
            for (int q = 0; q < 4; q++) acc[m][n][q] = 0.0f;

    uint4 aHX[2], aLX[2], bX[4], aHY[2], aLY[2], bY[4];

    auto loadA = [&](uint4* aH, uint4* aL, int ki) {
        long o = aBase + (long)ki * 512;
#pragma unroll
        for (int mf = 0; mf < 2; mf++) {
            aH[mf] = *(const uint4*)(AH + o + mf * ABLK);
            aL[mf] = *(const uint4*)(AL + o + mf * ABLK);
        }
    };
    auto loadB = [&](uint4* b, int ki) {
        long o = bBase + (long)ki * 512;
#pragma unroll
        for (int nf = 0; nf < 4; nf++)
            b[nf] = *(const uint4*)(B + o + nf * ABLK);
    };
    auto domma = [&](const uint4* aH, const uint4* aL, const uint4* b) {
#pragma unroll
        for (int nf = 0; nf < 4; nf++)
#pragma unroll
            for (int mf = 0; mf < 2; mf++) mma16816v(acc[mf][nf], aH[mf], b[nf].x, b[nf].y);
#pragma unroll
        for (int nf = 0; nf < 4; nf++)
#pragma unroll
            for (int mf = 0; mf < 2; mf++) mma16816v(acc[mf][nf], aH[mf], b[nf].z, b[nf].w);
#pragma unroll
        for (int nf = 0; nf < 4; nf++)
#pragma unroll
            for (int mf = 0; mf < 2; mf++) mma16816v(acc[mf][nf], aL[mf], b[nf].x, b[nf].y);
    };

    loadA(aHX, aLX, 0);
    loadB(bX, 0);
    for (int ki = 0; ki < 256; ki += 2) {
        loadA(aHY, aLY, ki + 1);
        loadB(bY, ki + 1);
        domma(aHX, aLX, bX);
        if (ki + 2 < 256) {
            loadA(aHX, aLX, ki + 2);
            loadB(bX, ki + 2);
        }
        domma(aHY, aLY, bY);
    }

    // epilogue: c0=(g,2t) c1=(g,2t+1) c2=(g+8,2t) c3=(g+8,2t+1)
#pragma unroll
    for (int mf = 0; mf < 2; mf++) {
#pragma unroll
        for (int nf = 0; nf < 4; nf++) {
            const float* c = acc[mf][nf];
            int row = blockIdx.x * 128 + wm * 32 + mf * 16 + g;
            int col = coff + blockIdx.y * 64 + wn * 32 + nf * 8 + 2 * t;
            uint32_t H0, L0, H1, L1;
            sp2(c[0], c[1], H0, L0);
            sp2(c[2], c[3], H1, L1);
            long o0 = (long)row * 2048 + col;
            long o1 = (long)(row + 8) * 2048 + col;
            *(uint32_t*)(msgH + o0) = H0;
            *(uint32_t*)(msgL + o0) = L0;
            *(uint32_t*)(msgH + o1) = H1;
            *(uint32_t*)(msgL + o1) = L1;
        }
    }
}

// ---------------------------------------------------------------------------
// GRU + LayerNorm
// ---------------------------------------------------------------------------
__device__ __forceinline__ float block_sum128(float v, float* red) {
#pragma unroll
    for (int o = 16; o; o >>= 1) v += __shfl_xor_sync(0xffffffffu, v, o);
    int lane = threadIdx.x & 31, w = threadIdx.x >> 5;
    if (lane == 0) red[w] = v;
    __syncthreads();
    float s = red[0] + red[1] + red[2] + red[3];
    __syncthreads();
    return s;
}

__global__ void gru_kernel(const float* __restrict__ gi, const float* __restrict__ gh,
                           const float* __restrict__ h,
                           const float* __restrict__ bx, const float* __restrict__ bh,
                           const float* __restrict__ gamma, const float* __restrict__ beta,
                           float* __restrict__ out,
                           bf16* __restrict__ outH, bf16* __restrict__ outL) {
    __shared__ float red[4];
    const int n = blockIdx.x;
    const int k = threadIdx.x;

    float gi0 = gi[(long)n * 384 + k];
    float gi1 = gi[(long)n * 384 + 128 + k];
    float gi2 = gi[(long)n * 384 + 256 + k];
    float gh0 = gh[(long)n * 384 + k];
    float gh1 = gh[(long)n * 384 + 128 + k];
    float gh2 = gh[(long)n * 384 + 256 + k];

    float xr = gi0 + bx[k]       + gh0 + bh[k];
    float xz = gi1 + bx[128 + k] + gh1 + bh[128 + k];
    float xi = gi2 + bx[256 + k];
    float xh = gh2 + bh[256 + k];

    float mean = block_sum128(xr, red) * (1.0f / 128.0f);
    float d = xr - mean;
    float var = block_sum128(d * d, red) * (1.0f / 128.0f);
    float yr = d * rsqrtf(var + 1e-5f) * gamma[k] + beta[k];
    float r = 1.0f / (1.0f + expf(-yr));

    mean = block_sum128(xz, red) * (1.0f / 128.0f);
    d = xz - mean;
    var = block_sum128(d * d, red) * (1.0f / 128.0f);
    float yz = d * rsqrtf(var + 1e-5f) * gamma[128 + k] + beta[128 + k];
    float z = 1.0f / (1.0f + expf(-yz));

    float xn = xi + r * xh;
    mean = block_sum128(xn, red) * (1.0f / 128.0f);
    d = xn - mean;
    var = block_sum128(d * d, red) * (1.0f / 128.0f);
    float yn = d * rsqrtf(var + 1e-5f) * gamma[256 + k] + beta[256 + k];
    float nn_ = tanhf(yn);

    float hv = h[(long)n * 128 + k];
    float o = (1.0f - z) * nn_ + z * hv;
    out[(long)n * 128 + k] = o;
    bf16 hh, ll;
    split_bf16(o, hh, ll);
    outH[(long)n * 128 + k] = hh;
    outL[(long)n * 128 + k] = ll;
}

// ---------------------------------------------------------------------------
// launch
// ---------------------------------------------------------------------------
static inline GP zeroGP() { GP p; memset(&p, 0, sizeof(p)); return p; }

extern "C" void kernel_launch(void* const* d_in, const int* in_sizes, int n_in,
                              void* d_out, int out_size) {
    (void)in_sizes; (void)n_in; (void)out_size;

    const float* adj    = (const float*)d_in[0];
    const float* states = (const float*)d_in[1];
    const int*   ids    = (const int*)  d_in[2];
    const float* emb    = (const float*)d_in[3];
    const float* W_init = (const float*)d_in[4];
    const float* b_init = (const float*)d_in[5];
    const float* W_out  = (const float*)d_in[6];
    const float* b_out  = (const float*)d_in[7];
    const float* W_in   = (const float*)d_in[8];
    const float* b_in   = (const float*)d_in[9];
    const float* Wx     = (const float*)d_in[10];
    const float* bx     = (const float*)d_in[11];
    const float* Wh     = (const float*)d_in[12];
    const float* bh     = (const float*)d_in[13];
    const float* gamma  = (const float*)d_in[14];
    const float* beta   = (const float*)d_in[15];
    float* out = (float*)d_out;

    bf16 *adjPH, *adjPL, *adjTPH, *adjTPL, *hoBP, *hiBP;
    bf16 *msgH, *msgL, *hH, *hL, *X0H, *X0L;
    bf16 *WinitH, *WinitL, *WoutH, *WoutL, *WinH, *WinL, *WxH, *WxL, *WhH, *WhL;
    float *hf, *gi, *gh;
    cudaGetSymbolAddress((void**)&adjPH, g_adjPH);
    cudaGetSymbolAddress((void**)&adjPL, g_adjPL);
    cudaGetSymbolAddress((void**)&adjTPH, g_adjTPH);
    cudaGetSymbolAddress((void**)&adjTPL, g_adjTPL);
    cudaGetSymbolAddress((void**)&hoBP, g_hoBP);
    cudaGetSymbolAddress((void**)&hiBP, g_hiBP);
    cudaGetSymbolAddress((void**)&msgH, g_msgH);
    cudaGetSymbolAddress((void**)&msgL, g_msgL);
    cudaGetSymbolAddress((void**)&hH, g_hH);
    cudaGetSymbolAddress((void**)&hL, g_hL);
    cudaGetSymbolAddress((void**)&X0H, g_X0H);
    cudaGetSymbolAddress((void**)&X0L, g_X0L);
    cudaGetSymbolAddress((void**)&WinitH, g_WinitH);
    cudaGetSymbolAddress((void**)&WinitL, g_WinitL);
    cudaGetSymbolAddress((void**)&WoutH, g_WoutH);
    cudaGetSymbolAddress((void**)&WoutL, g_WoutL);
    cudaGetSymbolAddress((void**)&WinH, g_WinH);
    cudaGetSymbolAddress((void**)&WinL, g_WinL);
    cudaGetSymbolAddress((void**)&WxH, g_WxH);
    cudaGetSymbolAddress((void**)&WxL, g_WxL);
    cudaGetSymbolAddress((void**)&WhH, g_WhH);
    cudaGetSymbolAddress((void**)&WhL, g_WhL);
    cudaGetSymbolAddress((void**)&hf, g_hf);
    cudaGetSymbolAddress((void**)&gi, g_gi);
    cudaGetSymbolAddress((void**)&gh, g_gh);

    cudaFuncSetAttribute(gemm_k, cudaFuncAttributeMaxDynamicSharedMemorySize, SMEM_BYTES);

    // 0: fused prep (adjacency pack + weight split + gather)
    {
        unsigned prepBlocks = (unsigned)((PREP_TASKS + 255) / 256);
        prep_kernel<<<PACK_BLOCKS + prepBlocks, 256>>>(
            adj, (char*)adjPH, (char*)adjPL, (char*)adjTPH, (char*)adjTPL,
            (const float4*)W_init, (const float4*)W_out, (const float4*)W_in,
            (const float4*)Wx, (const float4*)Wh,
            (uint2*)WinitH, (uint2*)WinitL, (uint2*)WoutH, (uint2*)WoutL,
            (uint2*)WinH, (uint2*)WinL, (uint2*)WxH, (uint2*)WxL,
            (uint2*)WhH, (uint2*)WhL,
            emb, ids, states, X0H, X0L);
    }

    // 1: h0 = tanh(X0 @ W_init + b_init)
    {
        GP p = zeroGP();
        p.AH = X0H; p.AL = X0L; p.BH = WinitH; p.BL = WinitL;
        p.bias = b_init; p.C = hf; p.CH = hH; p.CL = hL;
        p.K = 384; p.lda = 384; p.ldb = 128; p.ldc = 128;
        p.mode = 3;
        gemm_k<<<dim3(NN / 128, 1, 1), 256, SMEM_BYTES>>>(p);
    }

    for (int t = 0; t < TT; t++) {
        // 2/7: hoBP/hiBP = B-frag-packed tanh(h @ W + b), fused z=16
        {
            GP p = zeroGP();
            p.AH = hH; p.AL = hL;
            p.BH = WoutH; p.BL = WoutL; p.B2H = WinH; p.B2L = WinL;
            p.bias = b_out; p.bias2 = b_in;
            p.CH = hoBP; p.C2H = hiBP;
            p.K = HH; p.lda = HH; p.ldb = HH; p.ldc = HH;
            p.sB = (long)HH * HH;
            p.mode = 4; p.dual = 1;
            gemm_k<<<dim3(NN / 128, 1, 16), 256, SMEM_BYTES>>>(p);
        }
        // 3/8: messages — R12 adj_mma (PROFILED at t=0)
        adj_mma<<<dim3(NN / 128, 2, 16), 256>>>(
            (const char*)adjPH, (const char*)adjPL,
            (const char*)adjTPH, (const char*)adjTPL,
            (const char*)hoBP, (const char*)hiBP,
            msgH, msgL);
        // 4/9: gi = msg @ Wx
        {
            GP p = zeroGP();
            p.AH = msgH; p.AL = msgL; p.BH = WxH; p.BL = WxL;
            p.C = gi;
            p.K = 2048; p.lda = 2048; p.ldb = 384; p.ldc = 384;
            p.mode = 0;
            gemm_k<<<dim3(NN / 128, 3, 1), 256, SMEM_BYTES>>>(p);
        }
        // 5/10: gh = h @ Wh
        {
            GP p = zeroGP();
            p.AH = hH; p.AL = hL; p.BH = WhH; p.BL = WhL;
            p.C = gh;
            p.K = HH; p.lda = HH; p.ldb = 384; p.ldc = 384;
            p.mode = 0;
            gemm_k<<<dim3(NN / 128, 3, 1), 256, SMEM_BYTES>>>(p);
        }
        // 6/11: GRU
        float* hnext = (t == TT - 1) ? out : hf;
        gru_kernel<<<NN, 128>>>(gi, gh, hf, bx, bh, gamma, beta, hnext, hH, hL);
    }
}